// round 1
// baseline (speedup 1.0000x reference)
#include <cuda_runtime.h>

#define Bn 4
#define Cn 256
#define Hn 128
#define Wn 128
#define N_ROIS 512
#define Pn 7
#define SCALE_F 0.0625f
#define GAMMA_F 0.1f

// NHWC scratch: [B, H, W, C] = 16,777,216 floats (64 MB) static device buffer.
__device__ float g_xt[Bn * Hn * Wn * Cn];

// ---------------------------------------------------------------------------
// NCHW -> NHWC transpose. Tile 32 channels x 32 width per block, fixed (b,y).
// Reads coalesced along W, writes coalesced along C via shared tile.
// ---------------------------------------------------------------------------
__global__ void __launch_bounds__(256) transpose_nchw_nhwc(const float* __restrict__ x) {
    __shared__ float tile[32][33];
    const int bhy = blockIdx.z;          // b*H + y
    const int b = bhy >> 7;
    const int y = bhy & 127;
    const int w0 = blockIdx.x * 32;
    const int c0 = blockIdx.y * 32;

    const float* src = x + (((b * Cn + c0) * Hn + y) * Wn + w0);
#pragma unroll
    for (int i = threadIdx.y; i < 32; i += 8)
        tile[i][threadIdx.x] = src[i * (Hn * Wn) + threadIdx.x];
    __syncthreads();

    float* dst = g_xt + ((bhy * Wn + w0) * Cn + c0);
#pragma unroll
    for (int j = threadIdx.y; j < 32; j += 8)
        dst[j * Cn + threadIdx.x] = tile[threadIdx.x][j];
}

// ---------------------------------------------------------------------------
// Deformable ROI pool. One block per ROI, 256 threads = 256 channels.
// Per bin: separable 4x4 patch weights (validity + 1/16 mean folded in),
// computed once by threads 0..48, consumed by all channels.
// Output staged in shared (contiguous 12544-float ROI chunk), written coalesced.
// ---------------------------------------------------------------------------
__global__ void __launch_bounds__(256) dcn_pool_kernel(
    const float* __restrict__ rois,
    const float* __restrict__ offset,
    float* __restrict__ out)
{
    extern __shared__ float smem[];
    float* s_out = smem;                       // 12544 floats
    float* s_wy  = smem + Cn * 49;             // 49*4
    float* s_wx  = s_wy + 49 * 4;              // 49*4
    int*   s_rb  = (int*)(s_wx + 49 * 4);      // 49
    int*   s_cb  = s_rb + 49;                  // 49

    const int n = blockIdx.x;
    const int tid = threadIdx.x;

    const float rb0 = rois[n * 5 + 0];
    const float rx1 = rois[n * 5 + 1];
    const float ry1 = rois[n * 5 + 2];
    const float rx2 = rois[n * 5 + 3];
    const float ry2 = rois[n * 5 + 4];
    const int   bidx = (int)rb0;
    const float x1 = rx1 * SCALE_F - 0.5f;
    const float y1 = ry1 * SCALE_F - 0.5f;
    const float x2 = rx2 * SCALE_F - 0.5f;
    const float y2 = ry2 * SCALE_F - 0.5f;
    const float rw = fmaxf(x2 - x1, 1.0f);
    const float rh = fmaxf(y2 - y1, 1.0f);
    const float bw = rw * (1.0f / Pn);
    const float bh = rh * (1.0f / Pn);

    if (tid < 49) {
        const int ph = tid / 7;
        const int pw = tid - ph * 7;
        const float ox = offset[n * 98 + tid];
        const float oy = offset[n * 98 + 49 + tid];
        const float ybase = y1 + (float)ph * bh + GAMMA_F * rh * oy;
        const float xbase = x1 + (float)pw * bw + GAMMA_F * rw * ox;

        // ---- y direction: 4 samples -> weights over 4 contiguous rows ----
        float wy[4] = {0.f, 0.f, 0.f, 0.f};
        int   y0a[4];
        float lya[4], va[4];
        int rmin = Hn;
#pragma unroll
        for (int i = 0; i < 4; i++) {
            const float s  = ((float)i + 0.5f) * 0.25f;
            const float ys = ybase + s * bh;
            const float v  = (ys > -1.0f && ys < (float)Hn) ? 0.25f : 0.0f;
            const float yc = fminf(fmaxf(ys, 0.0f), (float)(Hn - 1));
            const int   y0 = (int)yc;       // yc >= 0 -> trunc == floor
            y0a[i] = y0; lya[i] = yc - (float)y0; va[i] = v;
            rmin = min(rmin, y0);
        }
#pragma unroll
        for (int i = 0; i < 4; i++) {
            const int sl0 = min(y0a[i] - rmin, 3);
            const int sl1 = min(min(y0a[i] + 1, Hn - 1) - rmin, 3);
            wy[sl0] += (1.0f - lya[i]) * va[i];
            wy[sl1] += lya[i] * va[i];
        }

        // ---- x direction ----
        float wx[4] = {0.f, 0.f, 0.f, 0.f};
        int   x0a[4];
        float lxa[4], vxa[4];
        int cmin = Wn;
#pragma unroll
        for (int j = 0; j < 4; j++) {
            const float s  = ((float)j + 0.5f) * 0.25f;
            const float xs = xbase + s * bw;
            const float v  = (xs > -1.0f && xs < (float)Wn) ? 0.25f : 0.0f;
            const float xc = fminf(fmaxf(xs, 0.0f), (float)(Wn - 1));
            const int   x0 = (int)xc;
            x0a[j] = x0; lxa[j] = xc - (float)x0; vxa[j] = v;
            cmin = min(cmin, x0);
        }
#pragma unroll
        for (int j = 0; j < 4; j++) {
            const int sl0 = min(x0a[j] - cmin, 3);
            const int sl1 = min(min(x0a[j] + 1, Wn - 1) - cmin, 3);
            wx[sl0] += (1.0f - lxa[j]) * vxa[j];
            wx[sl1] += lxa[j] * vxa[j];
        }

#pragma unroll
        for (int k = 0; k < 4; k++) {
            s_wy[tid * 4 + k] = wy[k];
            s_wx[tid * 4 + k] = wx[k];
        }
        s_rb[tid] = rmin;
        s_cb[tid] = cmin;
    }
    __syncthreads();

    // ---- gather: each thread owns channel c = tid ----
    const float* xb = g_xt + (bidx * Hn * Wn) * Cn + tid;

    for (int bin = 0; bin < 49; ++bin) {
        const int rbv = s_rb[bin];
        const int cbv = s_cb[bin];
        float wyv[4], wxv[4];
        int ro[4], co[4];
#pragma unroll
        for (int k = 0; k < 4; k++) {
            wyv[k] = s_wy[bin * 4 + k];
            wxv[k] = s_wx[bin * 4 + k];
            ro[k] = min(rbv + k, Hn - 1) * (Wn * Cn);
            co[k] = min(cbv + k, Wn - 1) * Cn;
        }
        float acc = 0.0f;
#pragma unroll
        for (int r = 0; r < 4; r++) {
            const float* rp = xb + ro[r];
            const float wr = wyv[r];
#pragma unroll
            for (int q = 0; q < 4; q++) {
                acc = fmaf(wr * wxv[q], __ldg(rp + co[q]), acc);
            }
        }
        s_out[tid * 49 + bin] = acc;   // stride 49 words: gcd(49,32)=1, conflict-free
    }
    __syncthreads();

    // ---- coalesced store of the ROI's contiguous output chunk ----
    float* o = out + n * (Cn * 49);
    for (int l = tid; l < Cn * 49; l += 256)
        o[l] = s_out[l];
}

extern "C" void kernel_launch(void* const* d_in, const int* in_sizes, int n_in,
                              void* d_out, int out_size) {
    const float* x      = (const float*)d_in[0];
    const float* rois   = (const float*)d_in[1];
    const float* offset = (const float*)d_in[2];
    float* out = (float*)d_out;

    // NCHW -> NHWC
    dim3 tgrid(Wn / 32, Cn / 32, Bn * Hn);
    transpose_nchw_nhwc<<<tgrid, dim3(32, 8)>>>(x);

    // Main pool kernel: dynamic smem = 12544 out + 49*8 weights + 49*2 bases
    const int smem_bytes = (Cn * 49 + 49 * 8) * sizeof(float) + 49 * 2 * sizeof(int);
    static bool attr_set = false;
    if (!attr_set) {
        cudaFuncSetAttribute(dcn_pool_kernel,
                             cudaFuncAttributeMaxDynamicSharedMemorySize, smem_bytes);
        attr_set = true;
    }
    dcn_pool_kernel<<<N_ROIS, 256, smem_bytes>>>(rois, offset, out);
}

// round 2
// speedup vs baseline: 1.7290x; 1.7290x over previous
#include <cuda_runtime.h>

#define Bn 4
#define Cn 256
#define Hn 128
#define Wn 128
#define N_ROIS 512
#define Pn 7
#define SCALE_F 0.0625f
#define GAMMA_F 0.1f

// NHWC scratch: [B, H, W, C] = 16,777,216 floats (64 MB)
__device__ float g_xt[Bn * Hn * Wn * Cn];

// ---------------------------------------------------------------------------
// NCHW -> NHWC transpose, float4 both directions.
// Block: 256 threads, handles 128 channels x 32 width at fixed (b,y),
// looping over 4 channel sub-tiles of 32.
// ---------------------------------------------------------------------------
__global__ void __launch_bounds__(256) transpose_nchw_nhwc(const float* __restrict__ x) {
    __shared__ float tile[32][33];
    const int bhy = blockIdx.z;          // b*H + y
    const int b = bhy >> 7;
    const int y = bhy & 127;
    const int w0 = blockIdx.x * 32;
    const int tid = threadIdx.x;

    const int cl = tid >> 3;             // 0..31 channel row (load)
    const int w4 = (tid & 7) * 4;        // 0..28 w quad (load)
    const int wl = tid >> 3;             // 0..31 w (store)
    const int c4 = (tid & 7) * 4;        // 0..28 c quad (store)

#pragma unroll
    for (int ct = 0; ct < 4; ct++) {
        const int c0 = blockIdx.y * 128 + ct * 32;
        const float4 v = *(const float4*)(x + (((size_t)(b * Cn + c0 + cl) * Hn + y) * Wn + w0 + w4));
        tile[cl][w4 + 0] = v.x;
        tile[cl][w4 + 1] = v.y;
        tile[cl][w4 + 2] = v.z;
        tile[cl][w4 + 3] = v.w;
        __syncthreads();
        float4 o;
        o.x = tile[c4 + 0][wl];
        o.y = tile[c4 + 1][wl];
        o.z = tile[c4 + 2][wl];
        o.w = tile[c4 + 3][wl];
        *(float4*)(g_xt + ((size_t)(bhy * Wn + w0 + wl) * Cn + c0 + c4)) = o;
        __syncthreads();
    }
}

// ---------------------------------------------------------------------------
// Deformable ROI pool. One block per ROI, 256 threads.
// Thread = (bin-slice bs = tid>>6) x (channel-quad c4 = tid&63).
// Setup (49 threads): separable 4x4 patch weights + 16 precomputed offsets
// and 16 combined weights per bin, stored in shared.
// Hot loop: 8 broadcast LDS.128 + 16 LDG.128 + 64 FFMA per bin.
// ---------------------------------------------------------------------------
#define SOUT_PITCH 260   // 49 rows of 260 (16B-aligned float4 rows, 257 < pad)

__global__ void __launch_bounds__(256) dcn_pool_kernel(
    const float* __restrict__ rois,
    const float* __restrict__ offset,
    float* __restrict__ out)
{
    extern __shared__ float smem[];
    float* s_out = smem;                           // 49*260 = 12740
    float* s_w   = smem + 49 * SOUT_PITCH;         // 49*16  = 784
    int*   s_off = (int*)(s_w + 49 * 16);          // 49*16  = 784

    const int n = blockIdx.x;
    const int tid = threadIdx.x;

    const float rb0 = rois[n * 5 + 0];
    const int   bidx = (int)rb0;

    if (tid < 49) {
        const float x1 = rois[n * 5 + 1] * SCALE_F - 0.5f;
        const float y1 = rois[n * 5 + 2] * SCALE_F - 0.5f;
        const float x2 = rois[n * 5 + 3] * SCALE_F - 0.5f;
        const float y2 = rois[n * 5 + 4] * SCALE_F - 0.5f;
        const float rw = fmaxf(x2 - x1, 1.0f);
        const float rh = fmaxf(y2 - y1, 1.0f);
        const float bw = rw * (1.0f / Pn);
        const float bh = rh * (1.0f / Pn);

        const int ph = tid / 7;
        const int pw = tid - ph * 7;
        const float ox = offset[n * 98 + tid];
        const float oy = offset[n * 98 + 49 + tid];
        const float ybase = y1 + (float)ph * bh + GAMMA_F * rh * oy;
        const float xbase = x1 + (float)pw * bw + GAMMA_F * rw * ox;

        // ---- y direction: 4 samples -> weights over 4 contiguous rows ----
        float wy[4] = {0.f, 0.f, 0.f, 0.f};
        int   y0a[4];
        float lya[4], va[4];
        int rmin = Hn;
#pragma unroll
        for (int i = 0; i < 4; i++) {
            const float s  = ((float)i + 0.5f) * 0.25f;
            const float ys = ybase + s * bh;
            const float v  = (ys > -1.0f && ys < (float)Hn) ? 0.25f : 0.0f;
            const float yc = fminf(fmaxf(ys, 0.0f), (float)(Hn - 1));
            const int   y0 = (int)yc;
            y0a[i] = y0; lya[i] = yc - (float)y0; va[i] = v;
            rmin = min(rmin, y0);
        }
#pragma unroll
        for (int i = 0; i < 4; i++) {
            const int sl0 = min(y0a[i] - rmin, 3);
            const int sl1 = min(min(y0a[i] + 1, Hn - 1) - rmin, 3);
            wy[sl0] += (1.0f - lya[i]) * va[i];
            wy[sl1] += lya[i] * va[i];
        }

        // ---- x direction ----
        float wx[4] = {0.f, 0.f, 0.f, 0.f};
        int   x0a[4];
        float lxa[4], vxa[4];
        int cmin = Wn;
#pragma unroll
        for (int j = 0; j < 4; j++) {
            const float s  = ((float)j + 0.5f) * 0.25f;
            const float xs = xbase + s * bw;
            const float v  = (xs > -1.0f && xs < (float)Wn) ? 0.25f : 0.0f;
            const float xc = fminf(fmaxf(xs, 0.0f), (float)(Wn - 1));
            const int   x0 = (int)xc;
            x0a[j] = x0; lxa[j] = xc - (float)x0; vxa[j] = v;
            cmin = min(cmin, x0);
        }
#pragma unroll
        for (int j = 0; j < 4; j++) {
            const int sl0 = min(x0a[j] - cmin, 3);
            const int sl1 = min(min(x0a[j] + 1, Wn - 1) - cmin, 3);
            wx[sl0] += (1.0f - lxa[j]) * vxa[j];
            wx[sl1] += lxa[j] * vxa[j];
        }

        // ---- combined 16 weights + 16 offsets ----
        int ro[4], co[4];
#pragma unroll
        for (int k = 0; k < 4; k++) {
            ro[k] = min(rmin + k, Hn - 1) * (Wn * Cn);
            co[k] = min(cmin + k, Wn - 1) * Cn;
        }
#pragma unroll
        for (int r = 0; r < 4; r++)
#pragma unroll
            for (int q = 0; q < 4; q++) {
                s_w  [tid * 16 + r * 4 + q] = wy[r] * wx[q];
                s_off[tid * 16 + r * 4 + q] = ro[r] + co[q];
            }
    }
    __syncthreads();

    // ---- gather ----
    const int c4 = tid & 63;        // channel quad: channels 4*c4 .. +3
    const int bs = tid >> 6;        // bin slice 0..3
    const float* base = g_xt + (size_t)(bidx * Hn * Wn) * Cn + c4 * 4;

    for (int bin = bs; bin < 49; bin += 4) {
        const float4* wv = (const float4*)(s_w   + bin * 16);
        const int4*   ov = (const int4*)  (s_off + bin * 16);
        float ax = 0.f, ay = 0.f, az = 0.f, aw = 0.f;
#pragma unroll
        for (int g = 0; g < 4; g++) {
            const float4 w = wv[g];
            const int4   o = ov[g];
            float4 v0 = *(const float4*)(base + o.x);
            float4 v1 = *(const float4*)(base + o.y);
            float4 v2 = *(const float4*)(base + o.z);
            float4 v3 = *(const float4*)(base + o.w);
            ax = fmaf(w.x, v0.x, ax); ay = fmaf(w.x, v0.y, ay);
            az = fmaf(w.x, v0.z, az); aw = fmaf(w.x, v0.w, aw);
            ax = fmaf(w.y, v1.x, ax); ay = fmaf(w.y, v1.y, ay);
            az = fmaf(w.y, v1.z, az); aw = fmaf(w.y, v1.w, aw);
            ax = fmaf(w.z, v2.x, ax); ay = fmaf(w.z, v2.y, ay);
            az = fmaf(w.z, v2.z, az); aw = fmaf(w.z, v2.w, aw);
            ax = fmaf(w.w, v3.x, ax); ay = fmaf(w.w, v3.y, ay);
            az = fmaf(w.w, v3.z, az); aw = fmaf(w.w, v3.w, aw);
        }
        float4 acc = make_float4(ax, ay, az, aw);
        *(float4*)(s_out + bin * SOUT_PITCH + c4 * 4) = acc;
    }
    __syncthreads();

    // ---- coalesced store of the ROI's contiguous [C][49] output chunk ----
    float* o = out + (size_t)n * (Cn * 49);
#pragma unroll
    for (int i = 0; i < 49; i++) {
        const int l = i * 256 + tid;          // l = c*49 + bin
        const int c = l / 49;
        const int bin = l - c * 49;
        o[l] = s_out[bin * SOUT_PITCH + c];
    }
}

extern "C" void kernel_launch(void* const* d_in, const int* in_sizes, int n_in,
                              void* d_out, int out_size) {
    const float* x      = (const float*)d_in[0];
    const float* rois   = (const float*)d_in[1];
    const float* offset = (const float*)d_in[2];
    float* out = (float*)d_out;

    // NCHW -> NHWC
    dim3 tgrid(Wn / 32, Cn / 128, Bn * Hn);
    transpose_nchw_nhwc<<<tgrid, 256>>>(x);

    const int smem_bytes = (49 * SOUT_PITCH + 49 * 16) * sizeof(float) + 49 * 16 * sizeof(int);
    static bool attr_set = false;
    if (!attr_set) {
        cudaFuncSetAttribute(dcn_pool_kernel,
                             cudaFuncAttributeMaxDynamicSharedMemorySize, smem_bytes);
        attr_set = true;
    }
    dcn_pool_kernel<<<N_ROIS, 256, smem_bytes>>>(rois, offset, out);
}